// round 1
// baseline (speedup 1.0000x reference)
#include <cuda_runtime.h>
#include <cstdint>

// GramsEmbedding: out[b,s,:] = sum over UNIQUE v in {idx[0,b,s], idx[1,b,s]} of weight[v,:]
// K=2, B=2, S=1024, V=32000, D=128.
//
// Each row of output (128 fp32 = 512B) is handled by 32 threads, one float4 each.
// ROWS = B*S = 2048; total threads = 2048*32 = 65536.

#define ROWS      2048      // B * S
#define D4        32        // 128 floats / 4 per float4
#define THREADS   256

__global__ __launch_bounds__(THREADS, 1)
void grams_embedding_kernel(const int* __restrict__ idx,
                            const float4* __restrict__ w4,   // [32000][32] float4
                            float4* __restrict__ out4)       // [2048][32] float4
{
    int t    = blockIdx.x * THREADS + threadIdx.x;   // 0 .. 65535
    int row  = t >> 5;                                // 0 .. 2047
    int lane = t & 31;                                // 0 .. 31

    int i0 = __ldg(&idx[row]);           // gram 0
    int i1 = __ldg(&idx[row + ROWS]);    // gram 1

    float4 a = __ldg(&w4[(long)i0 * D4 + lane]);
    if (i1 != i0) {
        float4 b = __ldg(&w4[(long)i1 * D4 + lane]);
        a.x += b.x; a.y += b.y; a.z += b.z; a.w += b.w;
    }
    out4[(long)row * D4 + lane] = a;
}

extern "C" void kernel_launch(void* const* d_in, const int* in_sizes, int n_in,
                              void* d_out, int out_size)
{
    // metadata order: input (int32, K*B*S = 4096), weight (float32, 32000*128)
    const int*    idx = (const int*)d_in[0];
    const float4* w4  = (const float4*)d_in[1];
    float4*       out = (float4*)d_out;

    const int total_threads = ROWS * D4;             // 65536
    grams_embedding_kernel<<<total_threads / THREADS, THREADS>>>(idx, w4, out);
}